// round 9
// baseline (speedup 1.0000x reference)
#include <cuda_runtime.h>

#define NSEG 16384
#define DFEAT 128
#define EPSV 1e-10f
#define RPW 64                  // rows per warp
#define RB 8                    // row batch (ILP depth)

// Scratch: __device__ globals are zero-initialized at module load; the GEMM
// epilogue re-zeros them after reading, so every execution sees zeros.
__device__ float g_pooled[NSEG * DFEAT];   // 8 MB
__device__ float g_denom[NSEG];

// ---------------------------------------------------------------------------
// Kernel 1: fused gate + weighted segment pooling.
// Per 8-row batch (lane l holds cols 4l..4l+3 of each row):
//  - 8 float4 loads (ILP)
//  - multi-value butterfly: 16 SHFLs reduce all 8 row-dots simultaneously
//    (rows merged pairwise with SEL each stage); lane l ends with the full
//    sum of row j(l) = 4*bit2(l) + 2*bit3(l) + bit4(l)
//  - each lane computes e = exp(p*ln(w)+g) for ITS row only: 2 MUFU instrs
//    per batch instead of 16 (w gathered per-lane from L1)
//  - 8 SHFL broadcasts deliver e[j] to all lanes for accumulation
// Sorted index => register accumulation, atomic flush at segment boundaries.
// ---------------------------------------------------------------------------
__global__ void __launch_bounds__(256) gate_pool_kernel(
    const float4* __restrict__ x4,        // [N, 32] float4 view of [N,128]
    const int*    __restrict__ index,     // [N] sorted
    const float*  __restrict__ weights,   // [N]
    const float*  __restrict__ gate_w,    // [128]
    const float*  __restrict__ gate_b,    // [1]
    const float*  __restrict__ pow_p,     // [1]
    int n_rows)
{
    const int lane = threadIdx.x & 31;
    const int warp_global = (blockIdx.x * blockDim.x + threadIdx.x) >> 5;
    const int row0 = warp_global * RPW;
    if (row0 >= n_rows) return;
    const int row_end = min(n_rows, row0 + RPW);

    const float4 gw = reinterpret_cast<const float4*>(gate_w)[lane];
    const float gb = __ldg(gate_b);
    const float p  = __ldg(pow_p);

    // lane -> row-within-batch handled by this lane's MUFU
    const int jmine = 4 * ((lane >> 2) & 1) + 2 * ((lane >> 3) & 1) + ((lane >> 4) & 1);
    // row j -> source lane holding e[j] (inverse of jmine map)
    const int SRC[RB] = {0, 16, 8, 24, 4, 20, 12, 28};

    float4 acc = make_float4(0.f, 0.f, 0.f, 0.f);
    float dsum = 0.f;
    int cur = __ldg(&index[row0]);

    auto flush = [&]() {
        float* dst = &g_pooled[cur * DFEAT + lane * 4];
        atomicAdd(dst + 0, acc.x);
        atomicAdd(dst + 1, acc.y);
        atomicAdd(dst + 2, acc.z);
        atomicAdd(dst + 3, acc.w);
        if (lane == 0) atomicAdd(&g_denom[cur], dsum);
        acc = make_float4(0.f, 0.f, 0.f, 0.f);
        dsum = 0.f;
    };

    int r = row0;
    for (; r + RB <= row_end; r += RB) {
        // ---- loads (8 in flight) ----
        float4 xv[RB];
        #pragma unroll
        for (int j = 0; j < RB; ++j)
            xv[j] = x4[(size_t)(r + j) * 32 + lane];
        const int segLast = __ldg(&index[r + RB - 1]);
        const float wmine = __ldg(&weights[r + jmine]);   // per-lane gather

        // ---- per-lane partial dots ----
        float pt[RB];
        #pragma unroll
        for (int j = 0; j < RB; ++j)
            pt[j] = xv[j].x * gw.x + xv[j].y * gw.y
                  + xv[j].z * gw.z + xv[j].w * gw.w;

        // ---- multi-value butterfly: 16 shfls for all 8 rows ----
        // stage A (off 16): 8 shfls, merge to 4 (row LSB <- lane bit4)
        float q[4];
        #pragma unroll
        for (int k = 0; k < 4; ++k) {
            const float t0 = pt[2 * k]     + __shfl_xor_sync(0xffffffffu, pt[2 * k], 16);
            const float t1 = pt[2 * k + 1] + __shfl_xor_sync(0xffffffffu, pt[2 * k + 1], 16);
            q[k] = (lane & 16) ? t1 : t0;
        }
        // stage B (off 8): 4 shfls, merge to 2 (next bit <- lane bit3)
        float rr2[2];
        #pragma unroll
        for (int m = 0; m < 2; ++m) {
            const float t0 = q[2 * m]     + __shfl_xor_sync(0xffffffffu, q[2 * m], 8);
            const float t1 = q[2 * m + 1] + __shfl_xor_sync(0xffffffffu, q[2 * m + 1], 8);
            rr2[m] = (lane & 8) ? t1 : t0;
        }
        // stage C (off 4): 2 shfls, merge to 1 (top bit <- lane bit2)
        float s;
        {
            const float t0 = rr2[0] + __shfl_xor_sync(0xffffffffu, rr2[0], 4);
            const float t1 = rr2[1] + __shfl_xor_sync(0xffffffffu, rr2[1], 4);
            s = (lane & 4) ? t1 : t0;
        }
        // stage D: finish within lane-quads (2 shfls)
        s += __shfl_xor_sync(0xffffffffu, s, 2);
        s += __shfl_xor_sync(0xffffffffu, s, 1);
        // lane l now holds the full dot of row jmine

        // ---- e for my row only: 2 MUFU instrs per warp-batch ----
        const float emine = __expf(__fmaf_rn(p, __logf(wmine), s + gb));

        // ---- broadcast e[j] to all lanes (8 shfls) ----
        float e[RB];
        #pragma unroll
        for (int j = 0; j < RB; ++j)
            e[j] = __shfl_sync(0xffffffffu, emine, SRC[j]);

        // ---- accumulate ----
        if (segLast == cur) {
            #pragma unroll
            for (int j = 0; j < RB; ++j) {
                acc.x += e[j] * xv[j].x;
                acc.y += e[j] * xv[j].y;
                acc.z += e[j] * xv[j].z;
                acc.w += e[j] * xv[j].w;
                dsum  += e[j];
            }
        } else {
            #pragma unroll
            for (int j = 0; j < RB; ++j) {
                const int seg = __ldg(&index[r + j]);   // L1-hot
                if (seg != cur) { flush(); cur = seg; }
                acc.x += e[j] * xv[j].x;
                acc.y += e[j] * xv[j].y;
                acc.z += e[j] * xv[j].z;
                acc.w += e[j] * xv[j].w;
                dsum  += e[j];
            }
        }
    }
    // ---- scalar tail ----
    for (; r < row_end; ++r) {
        const int seg = __ldg(&index[r]);
        const float4 xv = x4[(size_t)r * 32 + lane];
        const float w = __ldg(&weights[r]);
        float part = xv.x * gw.x + xv.y * gw.y + xv.z * gw.z + xv.w * gw.w;
        #pragma unroll
        for (int off = 16; off; off >>= 1)
            part += __shfl_xor_sync(0xffffffffu, part, off);
        const float e = __expf(__fmaf_rn(p, __logf(w), part + gb));
        if (seg != cur) { flush(); cur = seg; }
        acc.x += e * xv.x;
        acc.y += e * xv.y;
        acc.z += e * xv.z;
        acc.w += e * xv.w;
        dsum += e;
    }
    flush();
}

// ---------------------------------------------------------------------------
// Kernel 2: out[s] = (pooled[s]/(denom[s]+eps)) @ msg_w
//                    + (denom[s]/(denom[s]+eps)) * msg_b
// Also RE-ZEROS g_pooled / g_denom after reading (read-then-write), so the
// next execution's pool kernel sees zeroed scratch without a zero kernel.
// ---------------------------------------------------------------------------
__global__ void __launch_bounds__(256) out_gemm_kernel(
    const float* __restrict__ msg_w,      // [128,128] row-major (k, n)
    const float* __restrict__ msg_b,      // [128]
    float*       __restrict__ out)        // [NSEG,128]
{
    __shared__ float pr[16][DFEAT];
    __shared__ float dsh[16];
    __shared__ float gsh[16];

    const int s0 = blockIdx.x * 16;
    const int tid = threadIdx.x;

    if (tid < 16) {
        const float den = g_denom[s0 + tid];
        g_denom[s0 + tid] = 0.0f;               // re-zero for next run
        dsh[tid] = den + EPSV;
        gsh[tid] = den / (den + EPSV);
    }
    __syncthreads();

    #pragma unroll
    for (int i = tid; i < 16 * DFEAT; i += 256) {
        const int rr = i >> 7;
        const int cc = i & 127;
        const float v = g_pooled[(s0 + rr) * DFEAT + cc];
        g_pooled[(s0 + rr) * DFEAT + cc] = 0.0f; // re-zero for next run
        pr[rr][cc] = v / dsh[rr];
    }
    __syncthreads();

    const int c  = tid & 31;
    const int rg = tid >> 5;
    const int r0 = rg * 2;
    const int r1 = rg * 2 + 1;

    const float4* mw4 = reinterpret_cast<const float4*>(msg_w);
    const float4  mb  = reinterpret_cast<const float4*>(msg_b)[c];

    float4 a0 = make_float4(0.f, 0.f, 0.f, 0.f);
    float4 a1 = make_float4(0.f, 0.f, 0.f, 0.f);

    #pragma unroll 4
    for (int k = 0; k < DFEAT; ++k) {
        const float4 m = mw4[k * 32 + c];
        const float p0 = pr[r0][k];
        const float p1 = pr[r1][k];
        a0.x += p0 * m.x; a0.y += p0 * m.y; a0.z += p0 * m.z; a0.w += p0 * m.w;
        a1.x += p1 * m.x; a1.y += p1 * m.y; a1.z += p1 * m.z; a1.w += p1 * m.w;
    }

    const float g0 = gsh[r0];
    const float g1 = gsh[r1];
    float4 o0 = make_float4(a0.x + g0 * mb.x, a0.y + g0 * mb.y,
                            a0.z + g0 * mb.z, a0.w + g0 * mb.w);
    float4 o1 = make_float4(a1.x + g1 * mb.x, a1.y + g1 * mb.y,
                            a1.z + g1 * mb.z, a1.w + g1 * mb.w);

    reinterpret_cast<float4*>(out)[(size_t)(s0 + r0) * 32 + c] = o0;
    reinterpret_cast<float4*>(out)[(size_t)(s0 + r1) * 32 + c] = o1;
}

// ---------------------------------------------------------------------------
// Launch. Inputs: x, index, weights, gate_w, gate_b, msg_w, msg_b, pow_p.
// Output: [16384,128] f32.
// ---------------------------------------------------------------------------
extern "C" void kernel_launch(void* const* d_in, const int* in_sizes, int n_in,
                              void* d_out, int out_size)
{
    const float* x       = (const float*)d_in[0];
    const int*   index   = (const int*)  d_in[1];
    const float* weights = (const float*)d_in[2];
    const float* gate_w  = (const float*)d_in[3];
    const float* gate_b  = (const float*)d_in[4];
    const float* msg_w   = (const float*)d_in[5];
    const float* msg_b   = (const float*)d_in[6];
    const float* pow_p   = (const float*)d_in[7];
    float* out = (float*)d_out;

    const int n_rows = in_sizes[1];

    // 1) fused gate + pooling (scratch is zero: initially by static init,
    //    thereafter re-zeroed by out_gemm_kernel of the previous call)
    {
        const int n_warps  = (n_rows + RPW - 1) / RPW;
        const int n_blocks = (n_warps + 7) / 8;             // 8 warps / block
        gate_pool_kernel<<<n_blocks, 256>>>(
            (const float4*)x, index, weights, gate_w, gate_b, pow_p, n_rows);
    }

    // 2) small GEMM epilogue (+ scratch re-zero)
    out_gemm_kernel<<<NSEG / 16, 256>>>(msg_w, msg_b, out);
}

// round 10
// speedup vs baseline: 1.5506x; 1.5506x over previous
#include <cuda_runtime.h>

#define NSEG 16384
#define DFEAT 128
#define EPSV 1e-10f
#define RPW 64                  // rows per warp
#define RB 8                    // row batch (ILP depth)

// Scratch (allocation-free requirement -> __device__ globals)
__device__ float g_pooled[NSEG * DFEAT];   // 8 MB
__device__ float g_denom[NSEG];

// ---------------------------------------------------------------------------
// Kernel 0: zero the scratch accumulators (grid-stride float4, stores only)
// ---------------------------------------------------------------------------
__global__ void zero_scratch_kernel() {
    const int stride = gridDim.x * blockDim.x;
    const float4 z = make_float4(0.f, 0.f, 0.f, 0.f);
    float4* p4 = reinterpret_cast<float4*>(g_pooled);
    for (int i = blockIdx.x * blockDim.x + threadIdx.x;
         i < NSEG * DFEAT / 4; i += stride)
        p4[i] = z;
    float4* d4 = reinterpret_cast<float4*>(g_denom);
    for (int i = blockIdx.x * blockDim.x + threadIdx.x;
         i < NSEG / 4; i += stride)
        d4[i] = z;
}

// ---------------------------------------------------------------------------
// Kernel 1: fused gate + weighted segment pooling.
// Per 8-row batch (lane l holds cols 4l..4l+3 of each row):
//  - 8 float4 loads (ILP)
//  - multi-value butterfly: 16 SHFLs reduce all 8 row-dots simultaneously
//    (rows merged pairwise with SEL each stage); lane l ends with the full
//    sum of row j(l) = 4*bit2(l) + 2*bit3(l) + bit4(l)
//  - each lane computes e = exp(p*ln(w)+g) for ITS row only: 2 MUFU instrs
//    per batch instead of 16 (w gathered per-lane from L1)
//  - 8 SHFL broadcasts deliver e[j] to all lanes for accumulation
// Sorted index => register accumulation, atomic flush at segment boundaries.
// ---------------------------------------------------------------------------
__global__ void __launch_bounds__(256) gate_pool_kernel(
    const float4* __restrict__ x4,        // [N, 32] float4 view of [N,128]
    const int*    __restrict__ index,     // [N] sorted
    const float*  __restrict__ weights,   // [N]
    const float*  __restrict__ gate_w,    // [128]
    const float*  __restrict__ gate_b,    // [1]
    const float*  __restrict__ pow_p,     // [1]
    int n_rows)
{
    const int lane = threadIdx.x & 31;
    const int warp_global = (blockIdx.x * blockDim.x + threadIdx.x) >> 5;
    const int row0 = warp_global * RPW;
    if (row0 >= n_rows) return;
    const int row_end = min(n_rows, row0 + RPW);

    const float4 gw = reinterpret_cast<const float4*>(gate_w)[lane];
    const float gb = __ldg(gate_b);
    const float p  = __ldg(pow_p);

    // lane -> row-within-batch handled by this lane's MUFU
    const int jmine = 4 * ((lane >> 2) & 1) + 2 * ((lane >> 3) & 1) + ((lane >> 4) & 1);
    // row j -> source lane holding e[j] (inverse of jmine map)
    const int SRC[RB] = {0, 16, 8, 24, 4, 20, 12, 28};

    float4 acc = make_float4(0.f, 0.f, 0.f, 0.f);
    float dsum = 0.f;
    int cur = __ldg(&index[row0]);

    auto flush = [&]() {
        float* dst = &g_pooled[cur * DFEAT + lane * 4];
        atomicAdd(dst + 0, acc.x);
        atomicAdd(dst + 1, acc.y);
        atomicAdd(dst + 2, acc.z);
        atomicAdd(dst + 3, acc.w);
        if (lane == 0) atomicAdd(&g_denom[cur], dsum);
        acc = make_float4(0.f, 0.f, 0.f, 0.f);
        dsum = 0.f;
    };

    int r = row0;
    for (; r + RB <= row_end; r += RB) {
        // ---- loads (8 in flight) ----
        float4 xv[RB];
        #pragma unroll
        for (int j = 0; j < RB; ++j)
            xv[j] = x4[(size_t)(r + j) * 32 + lane];
        const int segLast = __ldg(&index[r + RB - 1]);
        const float wmine = __ldg(&weights[r + jmine]);   // per-lane gather

        // ---- per-lane partial dots ----
        float pt[RB];
        #pragma unroll
        for (int j = 0; j < RB; ++j)
            pt[j] = xv[j].x * gw.x + xv[j].y * gw.y
                  + xv[j].z * gw.z + xv[j].w * gw.w;

        // ---- multi-value butterfly: 16 shfls for all 8 rows ----
        float q[4];
        #pragma unroll
        for (int k = 0; k < 4; ++k) {
            const float t0 = pt[2 * k]     + __shfl_xor_sync(0xffffffffu, pt[2 * k], 16);
            const float t1 = pt[2 * k + 1] + __shfl_xor_sync(0xffffffffu, pt[2 * k + 1], 16);
            q[k] = (lane & 16) ? t1 : t0;
        }
        float rr2[2];
        #pragma unroll
        for (int m = 0; m < 2; ++m) {
            const float t0 = q[2 * m]     + __shfl_xor_sync(0xffffffffu, q[2 * m], 8);
            const float t1 = q[2 * m + 1] + __shfl_xor_sync(0xffffffffu, q[2 * m + 1], 8);
            rr2[m] = (lane & 8) ? t1 : t0;
        }
        float s;
        {
            const float t0 = rr2[0] + __shfl_xor_sync(0xffffffffu, rr2[0], 4);
            const float t1 = rr2[1] + __shfl_xor_sync(0xffffffffu, rr2[1], 4);
            s = (lane & 4) ? t1 : t0;
        }
        s += __shfl_xor_sync(0xffffffffu, s, 2);
        s += __shfl_xor_sync(0xffffffffu, s, 1);
        // lane l now holds the full dot of row jmine

        // ---- e for my row only: 2 MUFU instrs per warp-batch ----
        const float emine = __expf(__fmaf_rn(p, __logf(wmine), s + gb));

        // ---- broadcast e[j] to all lanes (8 shfls) ----
        float e[RB];
        #pragma unroll
        for (int j = 0; j < RB; ++j)
            e[j] = __shfl_sync(0xffffffffu, emine, SRC[j]);

        // ---- accumulate ----
        if (segLast == cur) {
            #pragma unroll
            for (int j = 0; j < RB; ++j) {
                acc.x += e[j] * xv[j].x;
                acc.y += e[j] * xv[j].y;
                acc.z += e[j] * xv[j].z;
                acc.w += e[j] * xv[j].w;
                dsum  += e[j];
            }
        } else {
            #pragma unroll
            for (int j = 0; j < RB; ++j) {
                const int seg = __ldg(&index[r + j]);   // L1-hot
                if (seg != cur) { flush(); cur = seg; }
                acc.x += e[j] * xv[j].x;
                acc.y += e[j] * xv[j].y;
                acc.z += e[j] * xv[j].z;
                acc.w += e[j] * xv[j].w;
                dsum  += e[j];
            }
        }
    }
    // ---- scalar tail ----
    for (; r < row_end; ++r) {
        const int seg = __ldg(&index[r]);
        const float4 xv = x4[(size_t)r * 32 + lane];
        const float w = __ldg(&weights[r]);
        float part = xv.x * gw.x + xv.y * gw.y + xv.z * gw.z + xv.w * gw.w;
        #pragma unroll
        for (int off = 16; off; off >>= 1)
            part += __shfl_xor_sync(0xffffffffu, part, off);
        const float e = __expf(__fmaf_rn(p, __logf(w), part + gb));
        if (seg != cur) { flush(); cur = seg; }
        acc.x += e * xv.x;
        acc.y += e * xv.y;
        acc.z += e * xv.z;
        acc.w += e * xv.w;
        dsum += e;
    }
    flush();
}

// ---------------------------------------------------------------------------
// Kernel 2: out[s] = (pooled[s]/(denom[s]+eps)) @ msg_w
//                    + (denom[s]/(denom[s]+eps)) * msg_b
// Pure reads of scratch (NO re-zero here — fusing the zeroing in made this
// kernel 14x slower in R8; the standalone zero kernel is the fast path).
// ---------------------------------------------------------------------------
__global__ void __launch_bounds__(256) out_gemm_kernel(
    const float* __restrict__ msg_w,      // [128,128] row-major (k, n)
    const float* __restrict__ msg_b,      // [128]
    float*       __restrict__ out)        // [NSEG,128]
{
    __shared__ float pr[16][DFEAT];
    __shared__ float dsh[16];
    __shared__ float gsh[16];

    const int s0 = blockIdx.x * 16;
    const int tid = threadIdx.x;

    if (tid < 16) {
        const float den = g_denom[s0 + tid];
        dsh[tid] = den + EPSV;
        gsh[tid] = den / (den + EPSV);
    }
    __syncthreads();

    #pragma unroll
    for (int i = tid; i < 16 * DFEAT; i += 256) {
        const int rr = i >> 7;
        const int cc = i & 127;
        pr[rr][cc] = g_pooled[(s0 + rr) * DFEAT + cc] / dsh[rr];
    }
    __syncthreads();

    const int c  = tid & 31;
    const int rg = tid >> 5;
    const int r0 = rg * 2;
    const int r1 = rg * 2 + 1;

    const float4* mw4 = reinterpret_cast<const float4*>(msg_w);
    const float4  mb  = reinterpret_cast<const float4*>(msg_b)[c];

    float4 a0 = make_float4(0.f, 0.f, 0.f, 0.f);
    float4 a1 = make_float4(0.f, 0.f, 0.f, 0.f);

    #pragma unroll 4
    for (int k = 0; k < DFEAT; ++k) {
        const float4 m = mw4[k * 32 + c];
        const float p0 = pr[r0][k];
        const float p1 = pr[r1][k];
        a0.x += p0 * m.x; a0.y += p0 * m.y; a0.z += p0 * m.z; a0.w += p0 * m.w;
        a1.x += p1 * m.x; a1.y += p1 * m.y; a1.z += p1 * m.z; a1.w += p1 * m.w;
    }

    const float g0 = gsh[r0];
    const float g1 = gsh[r1];
    float4 o0 = make_float4(a0.x + g0 * mb.x, a0.y + g0 * mb.y,
                            a0.z + g0 * mb.z, a0.w + g0 * mb.w);
    float4 o1 = make_float4(a1.x + g1 * mb.x, a1.y + g1 * mb.y,
                            a1.z + g1 * mb.z, a1.w + g1 * mb.w);

    reinterpret_cast<float4*>(out)[(size_t)(s0 + r0) * 32 + c] = o0;
    reinterpret_cast<float4*>(out)[(size_t)(s0 + r1) * 32 + c] = o1;
}

// ---------------------------------------------------------------------------
// Launch. Inputs: x, index, weights, gate_w, gate_b, msg_w, msg_b, pow_p.
// Output: [16384,128] f32.
// ---------------------------------------------------------------------------
extern "C" void kernel_launch(void* const* d_in, const int* in_sizes, int n_in,
                              void* d_out, int out_size)
{
    const float* x       = (const float*)d_in[0];
    const int*   index   = (const int*)  d_in[1];
    const float* weights = (const float*)d_in[2];
    const float* gate_w  = (const float*)d_in[3];
    const float* gate_b  = (const float*)d_in[4];
    const float* msg_w   = (const float*)d_in[5];
    const float* msg_b   = (const float*)d_in[6];
    const float* pow_p   = (const float*)d_in[7];
    float* out = (float*)d_out;

    const int n_rows = in_sizes[1];

    // 0) zero scratch
    zero_scratch_kernel<<<2048, 256>>>();

    // 1) fused gate + pooling
    {
        const int n_warps  = (n_rows + RPW - 1) / RPW;
        const int n_blocks = (n_warps + 7) / 8;             // 8 warps / block
        gate_pool_kernel<<<n_blocks, 256>>>(
            (const float4*)x, index, weights, gate_w, gate_b, pow_p, n_rows);
    }

    // 2) small GEMM epilogue
    out_gemm_kernel<<<NSEG / 16, 256>>>(msg_w, msg_b, out);
}

// round 12
// speedup vs baseline: 1.8243x; 1.1765x over previous
#include <cuda_runtime.h>

#define NSEG 16384
#define DFEAT 128
#define EPSV 1e-10f
#define RPW 64                  // rows per warp (pool kernel)
#define RB 8                    // row batch (ILP depth)
#define SEGB 32                 // segments per block (gemm kernel)
#define KP 64                   // k-panel rows (gemm kernel)

// Scratch (allocation-free requirement -> __device__ globals)
__device__ float g_pooled[NSEG * DFEAT];   // 8 MB
__device__ float g_denom[NSEG];

// ---------------------------------------------------------------------------
// Kernel 0: zero the scratch accumulators (grid-stride float4, stores only)
// ---------------------------------------------------------------------------
__global__ void zero_scratch_kernel() {
    const int stride = gridDim.x * blockDim.x;
    const float4 z = make_float4(0.f, 0.f, 0.f, 0.f);
    float4* p4 = reinterpret_cast<float4*>(g_pooled);
    for (int i = blockIdx.x * blockDim.x + threadIdx.x;
         i < NSEG * DFEAT / 4; i += stride)
        p4[i] = z;
    float4* d4 = reinterpret_cast<float4*>(g_denom);
    for (int i = blockIdx.x * blockDim.x + threadIdx.x;
         i < NSEG / 4; i += stride)
        d4[i] = z;
}

// ---------------------------------------------------------------------------
// Kernel 1: fused gate + weighted segment pooling (unchanged; evidence says
// this runs at ~8.5 TB/s, near roofline).
// ---------------------------------------------------------------------------
__global__ void __launch_bounds__(256) gate_pool_kernel(
    const float4* __restrict__ x4,        // [N, 32] float4 view of [N,128]
    const int*    __restrict__ index,     // [N] sorted
    const float*  __restrict__ weights,   // [N]
    const float*  __restrict__ gate_w,    // [128]
    const float*  __restrict__ gate_b,    // [1]
    const float*  __restrict__ pow_p,     // [1]
    int n_rows)
{
    const int lane = threadIdx.x & 31;
    const int warp_global = (blockIdx.x * blockDim.x + threadIdx.x) >> 5;
    const int row0 = warp_global * RPW;
    if (row0 >= n_rows) return;
    const int row_end = min(n_rows, row0 + RPW);

    const float4 gw = reinterpret_cast<const float4*>(gate_w)[lane];
    const float gb = __ldg(gate_b);
    const float p  = __ldg(pow_p);

    const int jmine = 4 * ((lane >> 2) & 1) + 2 * ((lane >> 3) & 1) + ((lane >> 4) & 1);
    const int SRC[RB] = {0, 16, 8, 24, 4, 20, 12, 28};

    float4 acc = make_float4(0.f, 0.f, 0.f, 0.f);
    float dsum = 0.f;
    int cur = __ldg(&index[row0]);

    auto flush = [&]() {
        float* dst = &g_pooled[cur * DFEAT + lane * 4];
        atomicAdd(dst + 0, acc.x);
        atomicAdd(dst + 1, acc.y);
        atomicAdd(dst + 2, acc.z);
        atomicAdd(dst + 3, acc.w);
        if (lane == 0) atomicAdd(&g_denom[cur], dsum);
        acc = make_float4(0.f, 0.f, 0.f, 0.f);
        dsum = 0.f;
    };

    int r = row0;
    for (; r + RB <= row_end; r += RB) {
        float4 xv[RB];
        #pragma unroll
        for (int j = 0; j < RB; ++j)
            xv[j] = x4[(size_t)(r + j) * 32 + lane];
        const int segLast = __ldg(&index[r + RB - 1]);
        const float wmine = __ldg(&weights[r + jmine]);

        float pt[RB];
        #pragma unroll
        for (int j = 0; j < RB; ++j)
            pt[j] = xv[j].x * gw.x + xv[j].y * gw.y
                  + xv[j].z * gw.z + xv[j].w * gw.w;

        float q[4];
        #pragma unroll
        for (int k = 0; k < 4; ++k) {
            const float t0 = pt[2 * k]     + __shfl_xor_sync(0xffffffffu, pt[2 * k], 16);
            const float t1 = pt[2 * k + 1] + __shfl_xor_sync(0xffffffffu, pt[2 * k + 1], 16);
            q[k] = (lane & 16) ? t1 : t0;
        }
        float rr2[2];
        #pragma unroll
        for (int m = 0; m < 2; ++m) {
            const float t0 = q[2 * m]     + __shfl_xor_sync(0xffffffffu, q[2 * m], 8);
            const float t1 = q[2 * m + 1] + __shfl_xor_sync(0xffffffffu, q[2 * m + 1], 8);
            rr2[m] = (lane & 8) ? t1 : t0;
        }
        float s;
        {
            const float t0 = rr2[0] + __shfl_xor_sync(0xffffffffu, rr2[0], 4);
            const float t1 = rr2[1] + __shfl_xor_sync(0xffffffffu, rr2[1], 4);
            s = (lane & 4) ? t1 : t0;
        }
        s += __shfl_xor_sync(0xffffffffu, s, 2);
        s += __shfl_xor_sync(0xffffffffu, s, 1);

        const float emine = __expf(__fmaf_rn(p, __logf(wmine), s + gb));

        float e[RB];
        #pragma unroll
        for (int j = 0; j < RB; ++j)
            e[j] = __shfl_sync(0xffffffffu, emine, SRC[j]);

        if (segLast == cur) {
            #pragma unroll
            for (int j = 0; j < RB; ++j) {
                acc.x += e[j] * xv[j].x;
                acc.y += e[j] * xv[j].y;
                acc.z += e[j] * xv[j].z;
                acc.w += e[j] * xv[j].w;
                dsum  += e[j];
            }
        } else {
            #pragma unroll
            for (int j = 0; j < RB; ++j) {
                const int seg = __ldg(&index[r + j]);
                if (seg != cur) { flush(); cur = seg; }
                acc.x += e[j] * xv[j].x;
                acc.y += e[j] * xv[j].y;
                acc.z += e[j] * xv[j].z;
                acc.w += e[j] * xv[j].w;
                dsum  += e[j];
            }
        }
    }
    for (; r < row_end; ++r) {
        const int seg = __ldg(&index[r]);
        const float4 xv = x4[(size_t)r * 32 + lane];
        const float w = __ldg(&weights[r]);
        float part = xv.x * gw.x + xv.y * gw.y + xv.z * gw.z + xv.w * gw.w;
        #pragma unroll
        for (int off = 16; off; off >>= 1)
            part += __shfl_xor_sync(0xffffffffu, part, off);
        const float e = __expf(__fmaf_rn(p, __logf(w), part + gb));
        if (seg != cur) { flush(); cur = seg; }
        acc.x += e * xv.x;
        acc.y += e * xv.y;
        acc.z += e * xv.z;
        acc.w += e * xv.w;
        dsum += e;
    }
    flush();
}

// ---------------------------------------------------------------------------
// Kernel 2: smem-blocked GEMM epilogue.
// The old per-thread L2-streaming version was the hidden ~65us hog (R9 ncu:
// DRAM 0.7%, issue 9.6% on its fused variant). Now: 32 segments/block
// (512 blocks); pr[32][128] normalized in smem; msg_w staged in two 64x128
// smem k-panels with full-block coalesced loads (deep MLP); each thread
// computes a 4-seg x 4-col register tile. Static smem = 48 KB.
// ---------------------------------------------------------------------------
__global__ void __launch_bounds__(256) out_gemm_kernel(
    const float* __restrict__ msg_w,      // [128,128] row-major (k, n)
    const float* __restrict__ msg_b,      // [128]
    float*       __restrict__ out)        // [NSEG,128]
{
    __shared__ float pr[SEGB][DFEAT];     // 16 KB  (normalized pooled rows)
    __shared__ float mw[KP][DFEAT];       // 32 KB  (msg_w k-panel; row 0
                                          //  doubles as den scratch early)
    const int s0 = blockIdx.x * SEGB;
    const int tid = threadIdx.x;
    const int cg = tid & 31;              // column group: 4 cols = cg*4..
    const int sg = tid >> 5;              // segment group: 4 segs = sg*4..

    // stage 1: den -> mw[0][0..31] (scratch before first panel load)
    if (tid < SEGB) mw[0][tid] = g_denom[s0 + tid];
    __syncthreads();

    // stage 2: build normalized pr = pooled / (den + eps)
    {
        const float4* gp4 = reinterpret_cast<const float4*>(g_pooled) + (size_t)s0 * 32;
        #pragma unroll
        for (int j = 0; j < 4; ++j) {
            const int idx = tid + j * 256;          // 0..1023 float4s
            const int rr = idx >> 5;
            const int cc = idx & 31;
            const float inv = __frcp_rn(mw[0][rr] + EPSV);
            const float4 v = gp4[idx];
            *reinterpret_cast<float4*>(&pr[rr][cc * 4]) =
                make_float4(v.x * inv, v.y * inv, v.z * inv, v.w * inv);
        }
    }

    float4 acc[4] = {
        make_float4(0.f, 0.f, 0.f, 0.f), make_float4(0.f, 0.f, 0.f, 0.f),
        make_float4(0.f, 0.f, 0.f, 0.f), make_float4(0.f, 0.f, 0.f, 0.f)};

    #pragma unroll
    for (int pnl = 0; pnl < DFEAT / KP; ++pnl) {
        __syncthreads();   // pr built / previous panel consumed (also protects den scratch)
        // load k-panel: 64x128 floats = 2048 float4, 8 per thread, coalesced
        {
            const float4* src = reinterpret_cast<const float4*>(msg_w) + pnl * KP * 32;
            #pragma unroll
            for (int j = 0; j < 8; ++j) {
                const int idx = tid + j * 256;      // 0..2047
                *reinterpret_cast<float4*>(&mw[idx >> 5][(idx & 31) * 4]) = src[idx];
            }
        }
        __syncthreads();

        // compute: 4 segs x 4 cols per thread
        #pragma unroll 2
        for (int kk = 0; kk < KP; ++kk) {
            const float4 m = *reinterpret_cast<const float4*>(&mw[kk][cg * 4]);
            const int k = pnl * KP + kk;
            #pragma unroll
            for (int i = 0; i < 4; ++i) {
                const float pv = pr[sg * 4 + i][k];
                acc[i].x += pv * m.x;
                acc[i].y += pv * m.y;
                acc[i].z += pv * m.z;
                acc[i].w += pv * m.w;
            }
        }
    }

    // epilogue: + (den/(den+eps)) * msg_b, write out
    const float4 mb = reinterpret_cast<const float4*>(msg_b)[cg];
    #pragma unroll
    for (int i = 0; i < 4; ++i) {
        const int seg = s0 + sg * 4 + i;
        const float den = __ldg(&g_denom[seg]);
        const float g = den / (den + EPSV);
        float4 o = make_float4(acc[i].x + g * mb.x, acc[i].y + g * mb.y,
                               acc[i].z + g * mb.z, acc[i].w + g * mb.w);
        reinterpret_cast<float4*>(out)[(size_t)seg * 32 + cg] = o;
    }
}

// ---------------------------------------------------------------------------
// Launch. Inputs: x, index, weights, gate_w, gate_b, msg_w, msg_b, pow_p.
// Output: [16384,128] f32.
// ---------------------------------------------------------------------------
extern "C" void kernel_launch(void* const* d_in, const int* in_sizes, int n_in,
                              void* d_out, int out_size)
{
    const float* x       = (const float*)d_in[0];
    const int*   index   = (const int*)  d_in[1];
    const float* weights = (const float*)d_in[2];
    const float* gate_w  = (const float*)d_in[3];
    const float* gate_b  = (const float*)d_in[4];
    const float* msg_w   = (const float*)d_in[5];
    const float* msg_b   = (const float*)d_in[6];
    const float* pow_p   = (const float*)d_in[7];
    float* out = (float*)d_out;

    const int n_rows = in_sizes[1];

    // 0) zero scratch
    zero_scratch_kernel<<<2048, 256>>>();

    // 1) fused gate + pooling
    {
        const int n_warps  = (n_rows + RPW - 1) / RPW;
        const int n_blocks = (n_warps + 7) / 8;             // 8 warps / block
        gate_pool_kernel<<<n_blocks, 256>>>(
            (const float4*)x, index, weights, gate_w, gate_b, pow_p, n_rows);
    }

    // 2) smem-blocked GEMM epilogue
    out_gemm_kernel<<<NSEG / SEGB, 256>>>(msg_w, msg_b, out);
}

// round 13
// speedup vs baseline: 1.8410x; 1.0091x over previous
#include <cuda_runtime.h>

#define NSEG 16384
#define DFEAT 128
#define EPSV 1e-10f
#define RPW 64                  // rows per warp (pool kernel)
#define RB 8                    // row batch (ILP depth)
#define SEGB 32                 // segments per block (gemm kernel)
#define KP 64                   // k-panel rows (gemm kernel)

// Scratch (allocation-free requirement -> __device__ globals).
// Zero-initialized at module load; out_gemm_kernel re-zeros its own slice
// (pure stores, after compute) so every call sees zeroed scratch.
__device__ float g_pooled[NSEG * DFEAT];   // 8 MB
__device__ float g_denom[NSEG];

// ---------------------------------------------------------------------------
// Kernel 1: fused gate + weighted segment pooling (frozen; near roofline).
// ---------------------------------------------------------------------------
__global__ void __launch_bounds__(256) gate_pool_kernel(
    const float4* __restrict__ x4,        // [N, 32] float4 view of [N,128]
    const int*    __restrict__ index,     // [N] sorted
    const float*  __restrict__ weights,   // [N]
    const float*  __restrict__ gate_w,    // [128]
    const float*  __restrict__ gate_b,    // [1]
    const float*  __restrict__ pow_p,     // [1]
    int n_rows)
{
    const int lane = threadIdx.x & 31;
    const int warp_global = (blockIdx.x * blockDim.x + threadIdx.x) >> 5;
    const int row0 = warp_global * RPW;
    if (row0 >= n_rows) return;
    const int row_end = min(n_rows, row0 + RPW);

    const float4 gw = reinterpret_cast<const float4*>(gate_w)[lane];
    const float gb = __ldg(gate_b);
    const float p  = __ldg(pow_p);

    const int jmine = 4 * ((lane >> 2) & 1) + 2 * ((lane >> 3) & 1) + ((lane >> 4) & 1);
    const int SRC[RB] = {0, 16, 8, 24, 4, 20, 12, 28};

    float4 acc = make_float4(0.f, 0.f, 0.f, 0.f);
    float dsum = 0.f;
    int cur = __ldg(&index[row0]);

    auto flush = [&]() {
        float* dst = &g_pooled[cur * DFEAT + lane * 4];
        atomicAdd(dst + 0, acc.x);
        atomicAdd(dst + 1, acc.y);
        atomicAdd(dst + 2, acc.z);
        atomicAdd(dst + 3, acc.w);
        if (lane == 0) atomicAdd(&g_denom[cur], dsum);
        acc = make_float4(0.f, 0.f, 0.f, 0.f);
        dsum = 0.f;
    };

    int r = row0;
    for (; r + RB <= row_end; r += RB) {
        float4 xv[RB];
        #pragma unroll
        for (int j = 0; j < RB; ++j)
            xv[j] = x4[(size_t)(r + j) * 32 + lane];
        const int segLast = __ldg(&index[r + RB - 1]);
        const float wmine = __ldg(&weights[r + jmine]);

        float pt[RB];
        #pragma unroll
        for (int j = 0; j < RB; ++j)
            pt[j] = xv[j].x * gw.x + xv[j].y * gw.y
                  + xv[j].z * gw.z + xv[j].w * gw.w;

        float q[4];
        #pragma unroll
        for (int k = 0; k < 4; ++k) {
            const float t0 = pt[2 * k]     + __shfl_xor_sync(0xffffffffu, pt[2 * k], 16);
            const float t1 = pt[2 * k + 1] + __shfl_xor_sync(0xffffffffu, pt[2 * k + 1], 16);
            q[k] = (lane & 16) ? t1 : t0;
        }
        float rr2[2];
        #pragma unroll
        for (int m = 0; m < 2; ++m) {
            const float t0 = q[2 * m]     + __shfl_xor_sync(0xffffffffu, q[2 * m], 8);
            const float t1 = q[2 * m + 1] + __shfl_xor_sync(0xffffffffu, q[2 * m + 1], 8);
            rr2[m] = (lane & 8) ? t1 : t0;
        }
        float s;
        {
            const float t0 = rr2[0] + __shfl_xor_sync(0xffffffffu, rr2[0], 4);
            const float t1 = rr2[1] + __shfl_xor_sync(0xffffffffu, rr2[1], 4);
            s = (lane & 4) ? t1 : t0;
        }
        s += __shfl_xor_sync(0xffffffffu, s, 2);
        s += __shfl_xor_sync(0xffffffffu, s, 1);

        const float emine = __expf(__fmaf_rn(p, __logf(wmine), s + gb));

        float e[RB];
        #pragma unroll
        for (int j = 0; j < RB; ++j)
            e[j] = __shfl_sync(0xffffffffu, emine, SRC[j]);

        if (segLast == cur) {
            #pragma unroll
            for (int j = 0; j < RB; ++j) {
                acc.x += e[j] * xv[j].x;
                acc.y += e[j] * xv[j].y;
                acc.z += e[j] * xv[j].z;
                acc.w += e[j] * xv[j].w;
                dsum  += e[j];
            }
        } else {
            #pragma unroll
            for (int j = 0; j < RB; ++j) {
                const int seg = __ldg(&index[r + j]);
                if (seg != cur) { flush(); cur = seg; }
                acc.x += e[j] * xv[j].x;
                acc.y += e[j] * xv[j].y;
                acc.z += e[j] * xv[j].z;
                acc.w += e[j] * xv[j].w;
                dsum  += e[j];
            }
        }
    }
    for (; r < row_end; ++r) {
        const int seg = __ldg(&index[r]);
        const float4 xv = x4[(size_t)r * 32 + lane];
        const float w = __ldg(&weights[r]);
        float part = xv.x * gw.x + xv.y * gw.y + xv.z * gw.z + xv.w * gw.w;
        #pragma unroll
        for (int off = 16; off; off >>= 1)
            part += __shfl_xor_sync(0xffffffffu, part, off);
        const float e = __expf(__fmaf_rn(p, __logf(w), part + gb));
        if (seg != cur) { flush(); cur = seg; }
        acc.x += e * xv.x;
        acc.y += e * xv.y;
        acc.z += e * xv.z;
        acc.w += e * xv.w;
        dsum += e;
    }
    flush();
}

// ---------------------------------------------------------------------------
// Kernel 2: smem-blocked GEMM epilogue + scratch re-zero tail.
// 32 segments/block (512 blocks); pr[32][128] normalized in smem; msg_w
// staged in 64x128 smem k-panels (coalesced full-block loads); 4-seg x 4-col
// register tiles. After all compute, each block re-zeros ITS OWN scratch
// slice with pure float4 stores (the safe store-only pattern; R8's slowdown
// came from interleaving loads+stores at kernel start, not from storing).
// ---------------------------------------------------------------------------
__global__ void __launch_bounds__(256) out_gemm_kernel(
    const float* __restrict__ msg_w,      // [128,128] row-major (k, n)
    const float* __restrict__ msg_b,      // [128]
    float*       __restrict__ out)        // [NSEG,128]
{
    __shared__ float pr[SEGB][DFEAT];     // 16 KB  (normalized pooled rows)
    __shared__ float mw[KP][DFEAT];       // 32 KB  (msg_w k-panel; row 0
                                          //  doubles as den scratch early)
    const int s0 = blockIdx.x * SEGB;
    const int tid = threadIdx.x;
    const int cg = tid & 31;              // column group: 4 cols = cg*4..
    const int sg = tid >> 5;              // segment group: 4 segs = sg*4..

    // stage 1: den -> mw[0][0..31] (scratch before first panel load)
    if (tid < SEGB) mw[0][tid] = g_denom[s0 + tid];
    __syncthreads();

    // per-thread bias gains for my 4 segments (registers, before mw reuse)
    float gbias[4];
    #pragma unroll
    for (int i = 0; i < 4; ++i) {
        const float den = mw[0][sg * 4 + i];
        gbias[i] = den / (den + EPSV);
    }

    // stage 2: build normalized pr = pooled / (den + eps)
    {
        const float4* gp4 = reinterpret_cast<const float4*>(g_pooled) + (size_t)s0 * 32;
        #pragma unroll
        for (int j = 0; j < 4; ++j) {
            const int idx = tid + j * 256;          // 0..1023 float4s
            const int rr = idx >> 5;
            const int cc = idx & 31;
            const float inv = __frcp_rn(mw[0][rr] + EPSV);
            const float4 v = gp4[idx];
            *reinterpret_cast<float4*>(&pr[rr][cc * 4]) =
                make_float4(v.x * inv, v.y * inv, v.z * inv, v.w * inv);
        }
    }

    float4 acc[4] = {
        make_float4(0.f, 0.f, 0.f, 0.f), make_float4(0.f, 0.f, 0.f, 0.f),
        make_float4(0.f, 0.f, 0.f, 0.f), make_float4(0.f, 0.f, 0.f, 0.f)};

    #pragma unroll
    for (int pnl = 0; pnl < DFEAT / KP; ++pnl) {
        __syncthreads();   // pr built / previous panel consumed / den scratch done
        // load k-panel: 64x128 floats = 2048 float4, 8 per thread, coalesced
        {
            const float4* src = reinterpret_cast<const float4*>(msg_w) + pnl * KP * 32;
            #pragma unroll
            for (int j = 0; j < 8; ++j) {
                const int idx = tid + j * 256;      // 0..2047
                *reinterpret_cast<float4*>(&mw[idx >> 5][(idx & 31) * 4]) = src[idx];
            }
        }
        __syncthreads();

        // compute: 4 segs x 4 cols per thread
        #pragma unroll 2
        for (int kk = 0; kk < KP; ++kk) {
            const float4 m = *reinterpret_cast<const float4*>(&mw[kk][cg * 4]);
            const int k = pnl * KP + kk;
            #pragma unroll
            for (int i = 0; i < 4; ++i) {
                const float pv = pr[sg * 4 + i][k];
                acc[i].x += pv * m.x;
                acc[i].y += pv * m.y;
                acc[i].z += pv * m.z;
                acc[i].w += pv * m.w;
            }
        }
    }

    // epilogue: + g * msg_b, write out
    const float4 mb = reinterpret_cast<const float4*>(msg_b)[cg];
    #pragma unroll
    for (int i = 0; i < 4; ++i) {
        const int seg = s0 + sg * 4 + i;
        float4 o = make_float4(acc[i].x + gbias[i] * mb.x,
                               acc[i].y + gbias[i] * mb.y,
                               acc[i].z + gbias[i] * mb.z,
                               acc[i].w + gbias[i] * mb.w);
        reinterpret_cast<float4*>(out)[(size_t)seg * 32 + cg] = o;
    }

    // tail: re-zero this block's scratch slice (pure stores; all reads of
    // g_pooled/g_denom by this block finished in stages 1-2)
    {
        const float4 z = make_float4(0.f, 0.f, 0.f, 0.f);
        float4* gp4 = reinterpret_cast<float4*>(g_pooled) + (size_t)s0 * 32;
        #pragma unroll
        for (int j = 0; j < 4; ++j)
            gp4[tid + j * 256] = z;
        if (tid < SEGB / 4)
            reinterpret_cast<float4*>(g_denom + s0)[tid] = z;
    }
}

// ---------------------------------------------------------------------------
// Launch (2 kernels). Inputs: x, index, weights, gate_w, gate_b, msg_w,
// msg_b, pow_p. Output: [16384,128] f32.
// ---------------------------------------------------------------------------
extern "C" void kernel_launch(void* const* d_in, const int* in_sizes, int n_in,
                              void* d_out, int out_size)
{
    const float* x       = (const float*)d_in[0];
    const int*   index   = (const int*)  d_in[1];
    const float* weights = (const float*)d_in[2];
    const float* gate_w  = (const float*)d_in[3];
    const float* gate_b  = (const float*)d_in[4];
    const float* msg_w   = (const float*)d_in[5];
    const float* msg_b   = (const float*)d_in[6];
    const float* pow_p   = (const float*)d_in[7];
    float* out = (float*)d_out;

    const int n_rows = in_sizes[1];

    // 1) fused gate + pooling (scratch zeroed by previous call's epilogue,
    //    or by static zero-init on the very first call)
    {
        const int n_warps  = (n_rows + RPW - 1) / RPW;
        const int n_blocks = (n_warps + 7) / 8;             // 8 warps / block
        gate_pool_kernel<<<n_blocks, 256>>>(
            (const float4*)x, index, weights, gate_w, gate_b, pow_p, n_rows);
    }

    // 2) smem-blocked GEMM epilogue + scratch re-zero
    out_gemm_kernel<<<NSEG / SEGB, 256>>>(msg_w, msg_b, out);
}

// round 14
// speedup vs baseline: 1.9898x; 1.0808x over previous
#include <cuda_runtime.h>

#define NSEG 16384
#define DFEAT 128
#define EPSV 1e-10f
#define RPW 64                  // rows per warp (pool kernel)
#define RB 8                    // row batch (ILP depth)
#define SEGB 32                 // segments per block (gemm kernel)
#define KP 64                   // k-panel rows (gemm kernel)

// Scratch (allocation-free requirement -> __device__ globals).
// Zero-initialized at module load; out_gemm_kernel re-zeros its own slice
// (pure stores, after compute) so every call sees zeroed scratch.
__device__ float g_pooled[NSEG * DFEAT];   // 8 MB
__device__ float g_denom[NSEG];

__device__ __forceinline__ float4 ldcs4(const float4* p) {
    return __ldcs(p);           // evict-first streaming load
}

// ---------------------------------------------------------------------------
// Kernel 1: fused gate + weighted segment pooling.
// Streaming x loads use __ldcs (x is read exactly once; keep L2 free for the
// scratch atomics). Otherwise frozen.
// ---------------------------------------------------------------------------
__global__ void __launch_bounds__(256) gate_pool_kernel(
    const float4* __restrict__ x4,        // [N, 32] float4 view of [N,128]
    const int*    __restrict__ index,     // [N] sorted
    const float*  __restrict__ weights,   // [N]
    const float*  __restrict__ gate_w,    // [128]
    const float*  __restrict__ gate_b,    // [1]
    const float*  __restrict__ pow_p,     // [1]
    int n_rows)
{
    const int lane = threadIdx.x & 31;
    const int warp_global = (blockIdx.x * blockDim.x + threadIdx.x) >> 5;
    const int row0 = warp_global * RPW;
    if (row0 >= n_rows) return;
    const int row_end = min(n_rows, row0 + RPW);

    const float4 gw = reinterpret_cast<const float4*>(gate_w)[lane];
    const float gb = __ldg(gate_b);
    const float p  = __ldg(pow_p);

    const int jmine = 4 * ((lane >> 2) & 1) + 2 * ((lane >> 3) & 1) + ((lane >> 4) & 1);
    const int SRC[RB] = {0, 16, 8, 24, 4, 20, 12, 28};

    float4 acc = make_float4(0.f, 0.f, 0.f, 0.f);
    float dsum = 0.f;
    int cur = __ldg(&index[row0]);

    auto flush = [&]() {
        float* dst = &g_pooled[cur * DFEAT + lane * 4];
        atomicAdd(dst + 0, acc.x);
        atomicAdd(dst + 1, acc.y);
        atomicAdd(dst + 2, acc.z);
        atomicAdd(dst + 3, acc.w);
        if (lane == 0) atomicAdd(&g_denom[cur], dsum);
        acc = make_float4(0.f, 0.f, 0.f, 0.f);
        dsum = 0.f;
    };

    int r = row0;
    for (; r + RB <= row_end; r += RB) {
        float4 xv[RB];
        #pragma unroll
        for (int j = 0; j < RB; ++j)
            xv[j] = ldcs4(&x4[(size_t)(r + j) * 32 + lane]);
        const int segLast = __ldg(&index[r + RB - 1]);
        const float wmine = __ldg(&weights[r + jmine]);

        float pt[RB];
        #pragma unroll
        for (int j = 0; j < RB; ++j)
            pt[j] = xv[j].x * gw.x + xv[j].y * gw.y
                  + xv[j].z * gw.z + xv[j].w * gw.w;

        float q[4];
        #pragma unroll
        for (int k = 0; k < 4; ++k) {
            const float t0 = pt[2 * k]     + __shfl_xor_sync(0xffffffffu, pt[2 * k], 16);
            const float t1 = pt[2 * k + 1] + __shfl_xor_sync(0xffffffffu, pt[2 * k + 1], 16);
            q[k] = (lane & 16) ? t1 : t0;
        }
        float rr2[2];
        #pragma unroll
        for (int m = 0; m < 2; ++m) {
            const float t0 = q[2 * m]     + __shfl_xor_sync(0xffffffffu, q[2 * m], 8);
            const float t1 = q[2 * m + 1] + __shfl_xor_sync(0xffffffffu, q[2 * m + 1], 8);
            rr2[m] = (lane & 8) ? t1 : t0;
        }
        float s;
        {
            const float t0 = rr2[0] + __shfl_xor_sync(0xffffffffu, rr2[0], 4);
            const float t1 = rr2[1] + __shfl_xor_sync(0xffffffffu, rr2[1], 4);
            s = (lane & 4) ? t1 : t0;
        }
        s += __shfl_xor_sync(0xffffffffu, s, 2);
        s += __shfl_xor_sync(0xffffffffu, s, 1);

        const float emine = __expf(__fmaf_rn(p, __logf(wmine), s + gb));

        float e[RB];
        #pragma unroll
        for (int j = 0; j < RB; ++j)
            e[j] = __shfl_sync(0xffffffffu, emine, SRC[j]);

        if (segLast == cur) {
            #pragma unroll
            for (int j = 0; j < RB; ++j) {
                acc.x += e[j] * xv[j].x;
                acc.y += e[j] * xv[j].y;
                acc.z += e[j] * xv[j].z;
                acc.w += e[j] * xv[j].w;
                dsum  += e[j];
            }
        } else {
            #pragma unroll
            for (int j = 0; j < RB; ++j) {
                const int seg = __ldg(&index[r + j]);
                if (seg != cur) { flush(); cur = seg; }
                acc.x += e[j] * xv[j].x;
                acc.y += e[j] * xv[j].y;
                acc.z += e[j] * xv[j].z;
                acc.w += e[j] * xv[j].w;
                dsum  += e[j];
            }
        }
    }
    for (; r < row_end; ++r) {
        const int seg = __ldg(&index[r]);
        const float4 xv = ldcs4(&x4[(size_t)r * 32 + lane]);
        const float w = __ldg(&weights[r]);
        float part = xv.x * gw.x + xv.y * gw.y + xv.z * gw.z + xv.w * gw.w;
        #pragma unroll
        for (int off = 16; off; off >>= 1)
            part += __shfl_xor_sync(0xffffffffu, part, off);
        const float e = __expf(__fmaf_rn(p, __logf(w), part + gb));
        if (seg != cur) { flush(); cur = seg; }
        acc.x += e * xv.x;
        acc.y += e * xv.y;
        acc.z += e * xv.z;
        acc.w += e * xv.w;
        dsum += e;
    }
    flush();
}

// ---------------------------------------------------------------------------
// Kernel 2: smem-blocked GEMM epilogue + scratch re-zero tail.
// R13 profile: L1 57% vs FMA 31% -> LDS-issue-bound. Now the k-loop steps by
// 4: per step, 4 LDS.128 of mw (conflict-free sweep) + 4 LDS.128 of pr
// (warp-broadcast) feed 64 FFMA -> 8 LDS.128 / 64 FFMA instead of 20 LDS.
// ---------------------------------------------------------------------------
__global__ void __launch_bounds__(256) out_gemm_kernel(
    const float* __restrict__ msg_w,      // [128,128] row-major (k, n)
    const float* __restrict__ msg_b,      // [128]
    float*       __restrict__ out)        // [NSEG,128]
{
    __shared__ float pr[SEGB][DFEAT];     // 16 KB  (normalized pooled rows)
    __shared__ float mw[KP][DFEAT];       // 32 KB  (msg_w k-panel; row 0
                                          //  doubles as den scratch early)
    const int s0 = blockIdx.x * SEGB;
    const int tid = threadIdx.x;
    const int cg = tid & 31;              // column group: 4 cols = cg*4..
    const int sg = tid >> 5;              // segment group: 4 segs = sg*4..

    // stage 1: den -> mw[0][0..31] (scratch before first panel load)
    if (tid < SEGB) mw[0][tid] = g_denom[s0 + tid];
    __syncthreads();

    // per-thread bias gains for my 4 segments (registers, before mw reuse)
    float gbias[4];
    #pragma unroll
    for (int i = 0; i < 4; ++i) {
        const float den = mw[0][sg * 4 + i];
        gbias[i] = den / (den + EPSV);
    }

    // stage 2: build normalized pr = pooled / (den + eps)
    {
        const float4* gp4 = reinterpret_cast<const float4*>(g_pooled) + (size_t)s0 * 32;
        #pragma unroll
        for (int j = 0; j < 4; ++j) {
            const int idx = tid + j * 256;          // 0..1023 float4s
            const int rr = idx >> 5;
            const int cc = idx & 31;
            const float inv = __frcp_rn(mw[0][rr] + EPSV);
            const float4 v = gp4[idx];
            *reinterpret_cast<float4*>(&pr[rr][cc * 4]) =
                make_float4(v.x * inv, v.y * inv, v.z * inv, v.w * inv);
        }
    }

    float4 acc[4] = {
        make_float4(0.f, 0.f, 0.f, 0.f), make_float4(0.f, 0.f, 0.f, 0.f),
        make_float4(0.f, 0.f, 0.f, 0.f), make_float4(0.f, 0.f, 0.f, 0.f)};

    #pragma unroll
    for (int pnl = 0; pnl < DFEAT / KP; ++pnl) {
        __syncthreads();   // pr built / previous panel consumed / den scratch done
        // load k-panel: 64x128 floats = 2048 float4, 8 per thread, coalesced
        {
            const float4* src = reinterpret_cast<const float4*>(msg_w) + pnl * KP * 32;
            #pragma unroll
            for (int j = 0; j < 8; ++j) {
                const int idx = tid + j * 256;      // 0..2047
                *reinterpret_cast<float4*>(&mw[idx >> 5][(idx & 31) * 4]) = src[idx];
            }
        }
        __syncthreads();

        // compute: k in steps of 4; vectorized LDS.128 for both operands
        #pragma unroll 4
        for (int kk = 0; kk < KP; kk += 4) {
            float4 m[4];
            #pragma unroll
            for (int t = 0; t < 4; ++t)
                m[t] = *reinterpret_cast<const float4*>(&mw[kk + t][cg * 4]);
            const int k = pnl * KP + kk;
            #pragma unroll
            for (int i = 0; i < 4; ++i) {
                const float4 pv = *reinterpret_cast<const float4*>(&pr[sg * 4 + i][k]);
                acc[i].x += pv.x * m[0].x; acc[i].y += pv.x * m[0].y;
                acc[i].z += pv.x * m[0].z; acc[i].w += pv.x * m[0].w;
                acc[i].x += pv.y * m[1].x; acc[i].y += pv.y * m[1].y;
                acc[i].z += pv.y * m[1].z; acc[i].w += pv.y * m[1].w;
                acc[i].x += pv.z * m[2].x; acc[i].y += pv.z * m[2].y;
                acc[i].z += pv.z * m[2].z; acc[i].w += pv.z * m[2].w;
                acc[i].x += pv.w * m[3].x; acc[i].y += pv.w * m[3].y;
                acc[i].z += pv.w * m[3].z; acc[i].w += pv.w * m[3].w;
            }
        }
    }

    // epilogue: + g * msg_b, write out
    const float4 mb = reinterpret_cast<const float4*>(msg_b)[cg];
    #pragma unroll
    for (int i = 0; i < 4; ++i) {
        const int seg = s0 + sg * 4 + i;
        float4 o = make_float4(acc[i].x + gbias[i] * mb.x,
                               acc[i].y + gbias[i] * mb.y,
                               acc[i].z + gbias[i] * mb.z,
                               acc[i].w + gbias[i] * mb.w);
        reinterpret_cast<float4*>(out)[(size_t)seg * 32 + cg] = o;
    }

    // tail: re-zero this block's scratch slice (pure stores; all reads of
    // g_pooled/g_denom by this block finished in stages 1-2)
    {
        const float4 z = make_float4(0.f, 0.f, 0.f, 0.f);
        float4* gp4 = reinterpret_cast<float4*>(g_pooled) + (size_t)s0 * 32;
        #pragma unroll
        for (int j = 0; j < 4; ++j)
            gp4[tid + j * 256] = z;
        if (tid < SEGB / 4)
            reinterpret_cast<float4*>(g_denom + s0)[tid] = z;
    }
}

// ---------------------------------------------------------------------------
// Launch (2 kernels). Inputs: x, index, weights, gate_w, gate_b, msg_w,
// msg_b, pow_p. Output: [16384,128] f32.
// ---------------------------------------------------------------------------
extern "C" void kernel_launch(void* const* d_in, const int* in_sizes, int n_in,
                              void* d_out, int out_size)
{
    const float* x       = (const float*)d_in[0];
    const int*   index   = (const int*)  d_in[1];
    const float* weights = (const float*)d_in[2];
    const float* gate_w  = (const float*)d_in[3];
    const float* gate_b  = (const float*)d_in[4];
    const float* msg_w   = (const float*)d_in[5];
    const float* msg_b   = (const float*)d_in[6];
    const float* pow_p   = (const float*)d_in[7];
    float* out = (float*)d_out;

    const int n_rows = in_sizes[1];

    // 1) fused gate + pooling (scratch zeroed by previous call's epilogue,
    //    or by static zero-init on the very first call)
    {
        const int n_warps  = (n_rows + RPW - 1) / RPW;
        const int n_blocks = (n_warps + 7) / 8;             // 8 warps / block
        gate_pool_kernel<<<n_blocks, 256>>>(
            (const float4*)x, index, weights, gate_w, gate_b, pow_p, n_rows);
    }

    // 2) smem-blocked GEMM epilogue + scratch re-zero
    out_gemm_kernel<<<NSEG / SEGB, 256>>>(msg_w, msg_b, out);
}